// round 1
// baseline (speedup 1.0000x reference)
#include <cuda_runtime.h>
#include <cuda_bf16.h>
#include <cstdint>

// Gather: out[g][row][j*32+k] = in[row][g*512 + j*64 + k]
//   g in [0,8), j in [0,8), k in [0,32), row in [0,16384)
// Output is the 8 group tensors concatenated flat:
//   out flat idx = g*(16384*256) + row*256 + j*32 + k
// All dims are powers of two -> pure shift/mask indexing.
// Work unit: one float4 (16B). Total float4s = 16384*2048/4 = 2^23.

__global__ void __launch_bounds__(256)
fuse_slice_cat_kernel(const float4* __restrict__ in, float4* __restrict__ out)
{
    // Each thread handles 4 float4s (grid-strided by a fixed stride) to cut
    // launch/index overhead while keeping full coalescing.
    unsigned int i = blockIdx.x * 256u + threadIdx.x;   // base float4 index
    const unsigned int stride = gridDim.x * 256u;       // = 2^21 with grid 8192

    #pragma unroll
    for (int it = 0; it < 4; ++it) {
        // i in [0, 2^23)
        unsigned int g   = i >> 20;          // group (0..7)
        unsigned int row = (i >> 6) & 16383; // row (0..16383); 64 float4 per row per group
        unsigned int v   = i & 63;           // float4 within the 256-col output row
        unsigned int j   = v >> 3;           // slice index (0..7); 8 float4 per 32-col slice
        unsigned int kq  = v & 7;            // float4 within slice

        // input row stride = 4096 floats = 1024 float4
        // input col (float4 units) = (g*512 + j*64)/4 + kq = g*128 + j*16 + kq
        unsigned int src = row * 1024u + g * 128u + j * 16u + kq;

        out[i] = in[src];
        i += stride;
    }
}

extern "C" void kernel_launch(void* const* d_in, const int* in_sizes, int n_in,
                              void* d_out, int out_size)
{
    const float4* in  = (const float4*)d_in[0];
    float4*       out = (float4*)d_out;

    // 2^23 float4s total; 4 per thread -> 2^21 threads -> 8192 blocks of 256.
    fuse_slice_cat_kernel<<<8192, 256>>>(in, out);
}